// round 7
// baseline (speedup 1.0000x reference)
#include <cuda_runtime.h>
#include <cstdint>

// Problem constants
// x: [B=256, R=1152, CIN=8]  -> A[256 x 9216]
// W: [N=10, R=1152, CIN=8, COUT=16] -> B[9216 x 160], col c = n*16+o
//   W element (n,k,o) at n*147456 + k*16 + o
// out: [10,256,1,1,16] = 40960 f32

#define M_DIM   256
#define K_DIM   9216
#define NC_DIM  160            // 10*16 combined columns
#define W_NSTR  147456         // 9216*16

#define MT      64             // M tile per block
#define KS      36             // K splits
#define KC      256            // K per block (9216/36)
#define KT      16             // K per smem stage
#define NIT     (KC / KT)      // 16 stages

// Partial sums scratch: [KS][256][160] = 5.9 MB (static device array: no allocs)
__device__ float g_partial[KS * M_DIM * NC_DIM];

__device__ __forceinline__ void fma2(unsigned long long& d,
                                     unsigned long long a,
                                     unsigned long long b) {
    asm("fma.rn.f32x2 %0, %1, %2, %0;" : "+l"(d) : "l"(a), "l"(b));
}

__device__ __forceinline__ unsigned long long dup_f32(float v) {
    unsigned long long r;
    unsigned int u = __float_as_uint(v);
    asm("mov.b64 %0, {%1, %1};" : "=l"(r) : "r"(u));
    return r;
}

__global__ void __launch_bounds__(256, 1)
caps_gemm_kernel(const float* __restrict__ X, const float* __restrict__ Wt) {
    __shared__ __align__(16) float sA[2][KT][MT];      // [k][m]  8 KB
    __shared__ __align__(16) float sB[2][KT][NC_DIM];  // [k][c] 20 KB

    const int t  = threadIdx.x;
    const int bx = blockIdx.x;
    const int mtile = bx & 3;        // 4 M tiles
    const int ks    = bx >> 2;       // 36 K slices
    const int M0 = mtile * MT;
    const int K0 = ks * KC;

    // compute-thread coords: 16 x 16, thread tile 4(m) x 10(c)
    const int tx = t & 15;           // c group (10 cols each)
    const int ty = t >> 4;           // m group (4 rows each)

    // A-load coords: each thread one float4 (64 rows x 16 k / 256 thr)
    const int aM  = t >> 2;          // 0..63
    const int aK4 = (t & 3) * 4;     // 0,4,8,12

    // B-load coords: 16 k rows x 160 cols / 256 thr -> 10 scalars each
    const int bK = t >> 4;           // 0..15
    const int bL = t & 15;           // 0..15 (o within a head)

    unsigned long long acc[4][5];
#pragma unroll
    for (int m = 0; m < 4; ++m)
#pragma unroll
        for (int j = 0; j < 5; ++j) acc[m][j] = 0ull;

    float4 aReg;
    float  bReg[10];

    // ---- prologue: load stage 0 -> smem buf 0 ----
    {
        const int kk = K0;
        aReg = *(const float4*)(X + (M0 + aM) * K_DIM + kk + aK4);
#pragma unroll
        for (int seg = 0; seg < 10; ++seg)
            bReg[seg] = Wt[seg * W_NSTR + (kk + bK) * 16 + bL];
        sA[0][aK4 + 0][aM] = aReg.x;
        sA[0][aK4 + 1][aM] = aReg.y;
        sA[0][aK4 + 2][aM] = aReg.z;
        sA[0][aK4 + 3][aM] = aReg.w;
#pragma unroll
        for (int seg = 0; seg < 10; ++seg)
            sB[0][bK][seg * 16 + bL] = bReg[seg];
    }

    for (int it = 0; it < NIT; ++it) {
        __syncthreads();   // buf[it&1] ready; buf[(it+1)&1] free

        // prefetch next stage into registers (hidden under compute)
        if (it + 1 < NIT) {
            const int kk = K0 + (it + 1) * KT;
            aReg = *(const float4*)(X + (M0 + aM) * K_DIM + kk + aK4);
#pragma unroll
            for (int seg = 0; seg < 10; ++seg)
                bReg[seg] = Wt[seg * W_NSTR + (kk + bK) * 16 + bL];
        }

        const int buf = it & 1;
#pragma unroll
        for (int k = 0; k < KT; ++k) {
            float4 a4 = *(const float4*)&sA[buf][k][ty * 4];
            const unsigned long long* bp =
                (const unsigned long long*)&sB[buf][k][tx * 10];
            unsigned long long b2[5];
#pragma unroll
            for (int j = 0; j < 5; ++j) b2[j] = bp[j];

            unsigned long long a2;
            a2 = dup_f32(a4.x);
#pragma unroll
            for (int j = 0; j < 5; ++j) fma2(acc[0][j], a2, b2[j]);
            a2 = dup_f32(a4.y);
#pragma unroll
            for (int j = 0; j < 5; ++j) fma2(acc[1][j], a2, b2[j]);
            a2 = dup_f32(a4.z);
#pragma unroll
            for (int j = 0; j < 5; ++j) fma2(acc[2][j], a2, b2[j]);
            a2 = dup_f32(a4.w);
#pragma unroll
            for (int j = 0; j < 5; ++j) fma2(acc[3][j], a2, b2[j]);
        }

        if (it + 1 < NIT) {
            const int nb = (it + 1) & 1;
            sA[nb][aK4 + 0][aM] = aReg.x;
            sA[nb][aK4 + 1][aM] = aReg.y;
            sA[nb][aK4 + 2][aM] = aReg.z;
            sA[nb][aK4 + 3][aM] = aReg.w;
#pragma unroll
            for (int seg = 0; seg < 10; ++seg)
                sB[nb][bK][seg * 16 + bL] = bReg[seg];
        }
    }

    // ---- epilogue: write partials (each slot written exactly once) ----
    float* base = g_partial + ks * (M_DIM * NC_DIM);
#pragma unroll
    for (int m = 0; m < 4; ++m) {
        float* row = base + (M0 + ty * 4 + m) * NC_DIM + tx * 10;
#pragma unroll
        for (int j = 0; j < 5; ++j) {
            float2 v;
            v.x = __uint_as_float((unsigned int)(acc[m][j] & 0xFFFFFFFFull));
            v.y = __uint_as_float((unsigned int)(acc[m][j] >> 32));
            *(float2*)(row + 2 * j) = v;
        }
    }
}

__global__ void __launch_bounds__(256)
caps_reduce_squash_kernel(float* __restrict__ out) {
    const int tid = blockIdx.x * 256 + threadIdx.x;  // 0..40959
    const int n   = tid >> 12;        // 0..9
    const int rem = tid & 4095;
    const int b   = rem >> 4;         // 0..255
    const int o   = rem & 15;         // 0..15

    const int idx = b * NC_DIM + n * 16 + o;
    float s = 0.f;
#pragma unroll
    for (int k = 0; k < KS; ++k)
        s += g_partial[k * (M_DIM * NC_DIM) + idx];
    s *= (1.0f / 1152.0f);

    // squash over the 16 o's (lanes 0..15 / 16..31 each form one (n,b) group)
    float sq = s * s;
#pragma unroll
    for (int w = 1; w < 16; w <<= 1)
        sq += __shfl_xor_sync(0xFFFFFFFFu, sq, w);

    const float scale = sqrtf(sq) / (1.0f + sq);
    out[tid] = s * scale;   // out laid out [n][b][1][1][o] = tid order
}

extern "C" void kernel_launch(void* const* d_in, const int* in_sizes, int n_in,
                              void* d_out, int out_size) {
    const float* X  = (const float*)d_in[0];
    const float* Wt = (const float*)d_in[1];
    // defensive: identify by element count (x: 2359296, W: 1474560)
    if (n_in >= 2 && in_sizes[0] == 10 * 1152 * 8 * 16) {
        const float* tmp = X; X = Wt; Wt = tmp;
    }

    caps_gemm_kernel<<<MT == 64 ? 4 * KS : 0, 256>>>(X, Wt);
    caps_reduce_squash_kernel<<<(10 * 256 * 16) / 256, 256>>>((float*)d_out);
}

// round 14
// speedup vs baseline: 1.3450x; 1.3450x over previous
#include <cuda_runtime.h>
#include <cuda_bf16.h>
#include <cstdint>

// Problem: x[B=256, R=1152, CIN=8] -> A[256 x 9216]
//          W[10,1152,8,16]         -> B[c=n*16+o][k] = [160 x 9216]
//          out[10,256,1,1,16]: s = (1/1152) * A @ B^T, squash over o(16)

#define MB      256
#define KD      9216
#define NC      160
#define W_NSTR  147456
#define KSPLIT  72
#define KCTA    128
#define MTILE   128

// ---------------- device scratch (static: no allocs) ----------------
__device__ __align__(16) __nv_bfloat16 g_Bh[NC * KD];   // 2.95 MB
__device__ __align__(16) __nv_bfloat16 g_Bl[NC * KD];
__device__ __align__(16) float g_partial[KSPLIT * MB * NC];  // 11.8 MB

// ---------------- helpers ----------------
__device__ __forceinline__ uint32_t smem_u32(const void* p) {
    uint32_t a;
    asm("{ .reg .u64 t; cvta.to.shared.u64 t, %1; cvt.u32.u64 %0, t; }"
        : "=r"(a) : "l"(p));
    return a;
}

__device__ __forceinline__ void ldsm_x4(uint32_t* r, uint32_t addr) {
    asm volatile("ldmatrix.sync.aligned.m8n8.x4.shared.b16 {%0,%1,%2,%3}, [%4];"
                 : "=r"(r[0]), "=r"(r[1]), "=r"(r[2]), "=r"(r[3]) : "r"(addr));
}

__device__ __forceinline__ void mma_bf16(float* d, const uint32_t* a,
                                         uint32_t b0, uint32_t b1) {
    asm volatile(
        "mma.sync.aligned.m16n8k16.row.col.f32.bf16.bf16.f32 "
        "{%0,%1,%2,%3}, {%4,%5,%6,%7}, {%8,%9}, {%0,%1,%2,%3};"
        : "+f"(d[0]), "+f"(d[1]), "+f"(d[2]), "+f"(d[3])
        : "r"(a[0]), "r"(a[1]), "r"(a[2]), "r"(a[3]), "r"(b0), "r"(b1));
}

__device__ __forceinline__ uint32_t pack_bf16(float a, float b) {
    __nv_bfloat162 h = __halves2bfloat162(__float2bfloat16(a), __float2bfloat16(b));
    return *(uint32_t*)&h;
}

// ---------------- kernel 1: transpose+split W -> B[c][k] hi/lo ----------------
__global__ void __launch_bounds__(256)
conv_w_kernel(const float* __restrict__ W) {
    __shared__ float s[576 * 17];                   // [kk][o] padded
    const int n  = blockIdx.y;                      // 0..9
    const int k0 = blockIdx.x * 576;                // 16 chunks cover 9216
    const float* src = W + (size_t)n * W_NSTR + (size_t)k0 * 16;
    for (int idx = threadIdx.x; idx < 9216; idx += 256) {
        int kk = idx >> 4, o = idx & 15;
        s[kk * 17 + o] = src[idx];
    }
    __syncthreads();
    const int o  = threadIdx.x >> 4;
    const int kl = threadIdx.x & 15;
    __nv_bfloat16* bh = g_Bh + (size_t)(n * 16 + o) * KD + k0;
    __nv_bfloat16* bl = g_Bl + (size_t)(n * 16 + o) * KD + k0;
#pragma unroll
    for (int i = 0; i < 36; ++i) {
        int kk = kl + 16 * i;
        float v = s[kk * 17 + o];
        __nv_bfloat16 h = __float2bfloat16(v);
        bh[kk] = h;
        bl[kk] = __float2bfloat16(v - __bfloat162float(h));
    }
}

// ---------------- kernel 2: warp-mma GEMM (split-K partials) ----------------
// smem (bytes): Ah[128x128]bf16 @0 (32K), Al @32768, Bh[160x128] @65536 (40K),
//               Bl @106496.  Swizzle: 16B chunk cs stored at (cs ^ (row&7)).
#define SA_H  0
#define SA_L  32768
#define SB_H  65536
#define SB_L  106496
#define GEMM_SMEM 147456

__global__ void __launch_bounds__(256, 1)
caps_gemm_mma(const float* __restrict__ X) {
    extern __shared__ char smem[];
    const uint32_t sb = smem_u32(smem);
    const int t  = threadIdx.x;
    const int mtile = blockIdx.x & 1;
    const int ks    = blockIdx.x >> 1;               // 0..71
    const int M0 = mtile * MTILE;
    const int K0 = ks * KCTA;

    // ---- fill A (convert f32 -> bf16 hi/lo in-flight): 2048 16B chunks ----
    {
        const float* xb = X + (size_t)M0 * KD + K0;
#pragma unroll
        for (int it = 0; it < 8; ++it) {
            int u = t + it * 256;
            int row = u >> 4, cs = u & 15;
            const float4* sp = (const float4*)(xb + (size_t)row * KD + cs * 8);
            float4 f0 = sp[0], f1 = sp[1];
            float h0 = __bfloat162float(__float2bfloat16(f0.x));
            float h1 = __bfloat162float(__float2bfloat16(f0.y));
            float h2 = __bfloat162float(__float2bfloat16(f0.z));
            float h3 = __bfloat162float(__float2bfloat16(f0.w));
            float h4 = __bfloat162float(__float2bfloat16(f1.x));
            float h5 = __bfloat162float(__float2bfloat16(f1.y));
            float h6 = __bfloat162float(__float2bfloat16(f1.z));
            float h7 = __bfloat162float(__float2bfloat16(f1.w));
            uint4 H, L;
            H.x = pack_bf16(f0.x, f0.y); H.y = pack_bf16(f0.z, f0.w);
            H.z = pack_bf16(f1.x, f1.y); H.w = pack_bf16(f1.z, f1.w);
            L.x = pack_bf16(f0.x - h0, f0.y - h1);
            L.y = pack_bf16(f0.z - h2, f0.w - h3);
            L.z = pack_bf16(f1.x - h4, f1.y - h5);
            L.w = pack_bf16(f1.z - h6, f1.w - h7);
            uint32_t off = row * 256 + ((cs ^ (row & 7)) << 4);
            *(uint4*)(smem + SA_H + off) = H;
            *(uint4*)(smem + SA_L + off) = L;
        }
    }
    // ---- fill B (already bf16): 2560 chunks each of hi/lo ----
#pragma unroll
    for (int it = 0; it < 10; ++it) {
        int u = t + it * 256;
        int row = u >> 4, cs = u & 15;
        size_t gsrc = (size_t)row * KD + K0 + cs * 8;
        uint32_t off = row * 256 + ((cs ^ (row & 7)) << 4);
        *(uint4*)(smem + SB_H + off) = *(const uint4*)(g_Bh + gsrc);
        *(uint4*)(smem + SB_L + off) = *(const uint4*)(g_Bl + gsrc);
    }
    __syncthreads();

    // ---- warp tiling: 8 warps = 4(M=32) x 2(N=80) ----
    const int l  = t & 31;
    const int wid = t >> 5;
    const int wm = wid >> 1;                 // 0..3
    const int wn = wid & 1;                  // 0..1

    float acc[2][10][4];
#pragma unroll
    for (int mt = 0; mt < 2; ++mt)
#pragma unroll
        for (int nt = 0; nt < 10; ++nt)
#pragma unroll
            for (int q = 0; q < 4; ++q) acc[mt][nt][q] = 0.f;

    // per-lane ldmatrix row coordinates (constant across steps)
    int rowA[2];
    rowA[0] = wm * 32 + (l & 15);
    rowA[1] = rowA[0] + 16;
    const int aKh = (l >> 4) & 1;            // k-half select for A
    int cB[5];
#pragma unroll
    for (int g = 0; g < 5; ++g)
        cB[g] = wn * 80 + g * 16 + ((l >> 4) & 1) * 8 + (l & 7);
    const int bKh = (l >> 3) & 1;            // k-half select for B

    const uint32_t aBase[3] = { sb + SA_H, sb + SA_H, sb + SA_L };
    const uint32_t bBase[3] = { sb + SB_H, sb + SB_L, sb + SB_H };

#pragma unroll
    for (int term = 0; term < 3; ++term) {
        const uint32_t aB = aBase[term], bB = bBase[term];
#pragma unroll
        for (int step = 0; step < 8; ++step) {
            uint32_t af[2][4], bf[5][4];
            const int csA = step * 2 + aKh;
            const int csB = step * 2 + bKh;
#pragma unroll
            for (int mt = 0; mt < 2; ++mt)
                ldsm_x4(af[mt], aB + rowA[mt] * 256 +
                                ((csA ^ (rowA[mt] & 7)) << 4));
#pragma unroll
            for (int g = 0; g < 5; ++g)
                ldsm_x4(bf[g], bB + cB[g] * 256 +
                               ((csB ^ (cB[g] & 7)) << 4));
#pragma unroll
            for (int mt = 0; mt < 2; ++mt)
#pragma unroll
                for (int nt = 0; nt < 10; ++nt) {
                    const int g = nt >> 1, h = nt & 1;
                    mma_bf16(acc[mt][nt], af[mt], bf[g][h * 2], bf[g][h * 2 + 1]);
                }
        }
    }

    // ---- epilogue: D fragments -> g_partial[ks][row][c] ----
    float* base = g_partial + (size_t)ks * (MB * NC);
#pragma unroll
    for (int mt = 0; mt < 2; ++mt) {
        const int r0 = M0 + wm * 32 + mt * 16 + (l >> 2);
#pragma unroll
        for (int nt = 0; nt < 10; ++nt) {
            const int c = wn * 80 + nt * 8 + (l & 3) * 2;
            float2 v0 = make_float2(acc[mt][nt][0], acc[mt][nt][1]);
            float2 v1 = make_float2(acc[mt][nt][2], acc[mt][nt][3]);
            *(float2*)(base + (size_t)r0 * NC + c)       = v0;
            *(float2*)(base + (size_t)(r0 + 8) * NC + c) = v1;
        }
    }
}

// ---------------- kernel 3: K-split reduce + squash ----------------
__global__ void __launch_bounds__(256)
caps_reduce_squash_kernel(float* __restrict__ out) {
    __shared__ float sred[4][64];
    const int t    = threadIdx.x;
    const int team = t >> 6;                 // 0..3, 18 splits each
    const int oi   = t & 63;
    const int p    = blockIdx.x * 64 + oi;   // flat index (b*160+c)

    float acc = 0.f;
    const float* src = g_partial + (size_t)(team * 18) * (MB * NC) + p;
#pragma unroll
    for (int s = 0; s < 18; ++s)
        acc += src[(size_t)s * (MB * NC)];
    sred[team][oi] = acc;
    __syncthreads();

    if (t < 64) {
        const int q = blockIdx.x * 64 + t;
        float s = (sred[0][t] + sred[1][t] + sred[2][t] + sred[3][t]) *
                  (1.0f / 1152.0f);
        float sq = s * s;
#pragma unroll
        for (int w = 1; w < 16; w <<= 1)
            sq += __shfl_xor_sync(0xFFFFFFFFu, sq, w);
        const float scale = sqrtf(sq) / (1.0f + sq);
        const int b = q / NC, rem = q % NC;
        const int n = rem >> 4, o = rem & 15;
        out[n * (MB * 16) + b * 16 + o] = s * scale;
    }
}

// ---------------- launch ----------------
extern "C" void kernel_launch(void* const* d_in, const int* in_sizes, int n_in,
                              void* d_out, int out_size) {
    const float* X  = (const float*)d_in[0];
    const float* Wt = (const float*)d_in[1];
    if (n_in >= 2 && in_sizes[0] == 10 * 1152 * 8 * 16) {
        const float* tmp = X; X = Wt; Wt = tmp;     // defensive order check
    }

    cudaFuncSetAttribute(caps_gemm_mma,
                         cudaFuncAttributeMaxDynamicSharedMemorySize,
                         GEMM_SMEM);

    conv_w_kernel<<<dim3(16, 10), 256>>>(Wt);
    caps_gemm_mma<<<2 * KSPLIT, 256, GEMM_SMEM>>>(X);
    caps_reduce_squash_kernel<<<(MB * NC) / 64, 256>>>((float*)d_out);
}

// round 15
// speedup vs baseline: 1.6467x; 1.2243x over previous
#include <cuda_runtime.h>
#include <cuda_bf16.h>
#include <cstdint>

// Problem: x[B=256, R=1152, CIN=8] -> A[256 x 9216]
//          W[10,1152,8,16]         -> B[c=n*16+o][k] = [160 x 9216]
//          out[10,256,1,1,16]: s = (1/1152) * A @ B^T, squash over o(16)

#define MB      256
#define KD      9216
#define NC      160
#define W_NSTR  147456
#define KSPLIT  72
#define KCTA    128
#define MTILE   128

// ---------------- device scratch (static: no allocs) ----------------
__device__ __align__(16) float g_partial[KSPLIT * MB * NC];  // 11.8 MB

// ---------------- helpers ----------------
__device__ __forceinline__ uint32_t smem_u32(const void* p) {
    uint32_t a;
    asm("{ .reg .u64 t; cvta.to.shared.u64 t, %1; cvt.u32.u64 %0, t; }"
        : "=r"(a) : "l"(p));
    return a;
}

__device__ __forceinline__ void ldsm_x4(uint32_t* r, uint32_t addr) {
    asm volatile("ldmatrix.sync.aligned.m8n8.x4.shared.b16 {%0,%1,%2,%3}, [%4];"
                 : "=r"(r[0]), "=r"(r[1]), "=r"(r[2]), "=r"(r[3]) : "r"(addr));
}

__device__ __forceinline__ void mma_bf16(float* d, const uint32_t* a,
                                         uint32_t b0, uint32_t b1) {
    asm volatile(
        "mma.sync.aligned.m16n8k16.row.col.f32.bf16.bf16.f32 "
        "{%0,%1,%2,%3}, {%4,%5,%6,%7}, {%8,%9}, {%0,%1,%2,%3};"
        : "+f"(d[0]), "+f"(d[1]), "+f"(d[2]), "+f"(d[3])
        : "r"(a[0]), "r"(a[1]), "r"(a[2]), "r"(a[3]), "r"(b0), "r"(b1));
}

__device__ __forceinline__ uint32_t pack_bf16(float a, float b) {
    __nv_bfloat162 h = __halves2bfloat162(__float2bfloat16(a), __float2bfloat16(b));
    return *(uint32_t*)&h;
}

// ---------------- fused GEMM: convert + warp-mma (split-K partials) -------
// Skew layout: tile row stride = 272 B (128 k * 2B + 16B skew).
// byte(row, k) = row*272 + (k>>3)*16 + (k&7)*2 ; bank phase = 16*((row+cs)%8)
#define RSTRIDE 272
#define SA_H  0
#define SA_L  34816          // 128*272
#define SB_H  69632
#define SB_L  113152         // +160*272
#define GEMM_SMEM 156672

__global__ void __launch_bounds__(256, 1)
caps_gemm_mma(const float* __restrict__ X, const float* __restrict__ W) {
    extern __shared__ char smem[];
    const uint32_t sb = smem_u32(smem);
    const int t  = threadIdx.x;
    const int mtile = blockIdx.x & 1;
    const int ks    = blockIdx.x >> 1;               // 0..71
    const int M0 = mtile * MTILE;
    const int K0 = ks * KCTA;

    // ---- fill A: f32 -> bf16 hi/lo in-flight (2048 16B chunks) ----
    {
        const float* xb = X + (size_t)M0 * KD + K0;
#pragma unroll
        for (int it = 0; it < 8; ++it) {
            int u = t + it * 256;
            int row = u >> 4, cs = u & 15;
            const float4* sp = (const float4*)(xb + (size_t)row * KD + cs * 8);
            float4 f0 = sp[0], f1 = sp[1];
            float h0 = __bfloat162float(__float2bfloat16(f0.x));
            float h1 = __bfloat162float(__float2bfloat16(f0.y));
            float h2 = __bfloat162float(__float2bfloat16(f0.z));
            float h3 = __bfloat162float(__float2bfloat16(f0.w));
            float h4 = __bfloat162float(__float2bfloat16(f1.x));
            float h5 = __bfloat162float(__float2bfloat16(f1.y));
            float h6 = __bfloat162float(__float2bfloat16(f1.z));
            float h7 = __bfloat162float(__float2bfloat16(f1.w));
            uint4 H, L;
            H.x = pack_bf16(f0.x, f0.y); H.y = pack_bf16(f0.z, f0.w);
            H.z = pack_bf16(f1.x, f1.y); H.w = pack_bf16(f1.z, f1.w);
            L.x = pack_bf16(f0.x - h0, f0.y - h1);
            L.y = pack_bf16(f0.z - h2, f0.w - h3);
            L.z = pack_bf16(f1.x - h4, f1.y - h5);
            L.w = pack_bf16(f1.z - h6, f1.w - h7);
            uint32_t off = row * RSTRIDE + (cs << 4);
            *(uint4*)(smem + SA_H + off) = H;
            *(uint4*)(smem + SA_L + off) = L;
        }
    }

    // ---- fill B from W: transpose + split (2560 (c,koct) chunks) ----
    // lane handles (c = n*16+o, koct): gathers 8 k's, stores one 16B chunk.
#pragma unroll
    for (int i = 0; i < 10; ++i) {
        int idx  = t + i * 256;          // 0..2559
        int koct = idx / NC;             // 0..15
        int c    = idx - koct * NC;      // 0..159
        int n = c >> 4, o = c & 15;
        const float* wp = W + (size_t)n * W_NSTR +
                          (size_t)(K0 + koct * 8) * 16 + o;
        float f[8];
#pragma unroll
        for (int j = 0; j < 8; ++j) f[j] = wp[j * 16];
        float h[8];
#pragma unroll
        for (int j = 0; j < 8; ++j)
            h[j] = __bfloat162float(__float2bfloat16(f[j]));
        uint4 H, L;
        H.x = pack_bf16(f[0], f[1]); H.y = pack_bf16(f[2], f[3]);
        H.z = pack_bf16(f[4], f[5]); H.w = pack_bf16(f[6], f[7]);
        L.x = pack_bf16(f[0] - h[0], f[1] - h[1]);
        L.y = pack_bf16(f[2] - h[2], f[3] - h[3]);
        L.z = pack_bf16(f[4] - h[4], f[5] - h[5]);
        L.w = pack_bf16(f[6] - h[6], f[7] - h[7]);
        uint32_t off = c * RSTRIDE + (koct << 4);
        *(uint4*)(smem + SB_H + off) = H;
        *(uint4*)(smem + SB_L + off) = L;
    }
    __syncthreads();

    // ---- warp tiling: 8 warps = 4(M=32) x 2(N=80) ----
    const int l  = t & 31;
    const int wid = t >> 5;
    const int wm = wid >> 1;                 // 0..3
    const int wn = wid & 1;                  // 0..1

    float acc[2][10][4];
#pragma unroll
    for (int mt = 0; mt < 2; ++mt)
#pragma unroll
        for (int nt = 0; nt < 10; ++nt)
#pragma unroll
            for (int q = 0; q < 4; ++q) acc[mt][nt][q] = 0.f;

    // per-lane base addresses (affine in step: +32B per k16-step)
    const int aKh = (l >> 4) & 1;
    const int bKh = (l >> 3) & 1;
    uint32_t adA[2], adB[5];
    {
        int r0 = wm * 32 + (l & 15);
        adA[0] = r0 * RSTRIDE + (aKh << 4);
        adA[1] = (r0 + 16) * RSTRIDE + (aKh << 4);
#pragma unroll
        for (int g = 0; g < 5; ++g) {
            int c = wn * 80 + g * 16 + ((l >> 4) & 1) * 8 + (l & 7);
            adB[g] = c * RSTRIDE + (bKh << 4);
        }
    }

    const uint32_t aBase[3] = { sb + SA_H, sb + SA_H, sb + SA_L };
    const uint32_t bBase[3] = { sb + SB_H, sb + SB_L, sb + SB_H };

#pragma unroll
    for (int term = 0; term < 3; ++term) {
        const uint32_t aB = aBase[term], bB = bBase[term];
#pragma unroll
        for (int step = 0; step < 8; ++step) {
            uint32_t af[2][4], bf[5][4];
#pragma unroll
            for (int mt = 0; mt < 2; ++mt)
                ldsm_x4(af[mt], aB + adA[mt] + step * 32);
#pragma unroll
            for (int g = 0; g < 5; ++g)
                ldsm_x4(bf[g], bB + adB[g] + step * 32);
#pragma unroll
            for (int mt = 0; mt < 2; ++mt)
#pragma unroll
                for (int nt = 0; nt < 10; ++nt) {
                    const int g = nt >> 1, h = nt & 1;
                    mma_bf16(acc[mt][nt], af[mt], bf[g][h * 2], bf[g][h * 2 + 1]);
                }
        }
    }

    // ---- epilogue: D fragments -> g_partial[ks][row][c] ----
    float* base = g_partial + (size_t)ks * (MB * NC);
#pragma unroll
    for (int mt = 0; mt < 2; ++mt) {
        const int r0 = M0 + wm * 32 + mt * 16 + (l >> 2);
#pragma unroll
        for (int nt = 0; nt < 10; ++nt) {
            const int c = wn * 80 + nt * 8 + (l & 3) * 2;
            float2 v0 = make_float2(acc[mt][nt][0], acc[mt][nt][1]);
            float2 v1 = make_float2(acc[mt][nt][2], acc[mt][nt][3]);
            *(float2*)(base + (size_t)r0 * NC + c)       = v0;
            *(float2*)(base + (size_t)(r0 + 8) * NC + c) = v1;
        }
    }
}

// ---------------- reduce + squash ----------------
__global__ void __launch_bounds__(256)
caps_reduce_squash_kernel(float* __restrict__ out) {
    __shared__ float sred[4][64];
    const int t    = threadIdx.x;
    const int team = t >> 6;                 // 0..3, 18 splits each
    const int oi   = t & 63;
    const int p    = blockIdx.x * 64 + oi;   // flat index (b*160+c)

    float acc = 0.f;
    const float* src = g_partial + (size_t)(team * 18) * (MB * NC) + p;
#pragma unroll
    for (int s = 0; s < 18; ++s)
        acc += src[(size_t)s * (MB * NC)];
    sred[team][oi] = acc;
    __syncthreads();

    if (t < 64) {
        const int q = blockIdx.x * 64 + t;
        float s = (sred[0][t] + sred[1][t] + sred[2][t] + sred[3][t]) *
                  (1.0f / 1152.0f);
        float sq = s * s;
#pragma unroll
        for (int w = 1; w < 16; w <<= 1)
            sq += __shfl_xor_sync(0xFFFFFFFFu, sq, w);
        const float scale = sqrtf(sq) / (1.0f + sq);
        const int b = q / NC, rem = q % NC;
        const int n = rem >> 4, o = rem & 15;
        out[n * (MB * 16) + b * 16 + o] = s * scale;
    }
}

// ---------------- launch ----------------
extern "C" void kernel_launch(void* const* d_in, const int* in_sizes, int n_in,
                              void* d_out, int out_size) {
    const float* X  = (const float*)d_in[0];
    const float* Wt = (const float*)d_in[1];
    if (n_in >= 2 && in_sizes[0] == 10 * 1152 * 8 * 16) {
        const float* tmp = X; X = Wt; Wt = tmp;     // defensive order check
    }

    cudaFuncSetAttribute(caps_gemm_mma,
                         cudaFuncAttributeMaxDynamicSharedMemorySize,
                         GEMM_SMEM);

    caps_gemm_mma<<<2 * KSPLIT, 256, GEMM_SMEM>>>(X, Wt);
    caps_reduce_squash_kernel<<<(MB * NC) / 64, 256>>>((float*)d_out);
}